// round 16
// baseline (speedup 1.0000x reference)
#include <cuda_runtime.h>
#include <cuda_fp16.h>
#include <cstdint>

// Fourier-KAN: out[b,o] = bias[o] + sum_{i,k} cos(k x[b,i]) c0[i,o,k-1] + sin(k x) c1[i,o,k-1]
// B=32768, I=512, O=64, G=8  ->  GEMM M=32768, N=64, K=8192, fp16 features on the fly.
// R16 = R15 (best: 118.8us) with KC doubled to 128: half the handshakes/waits/loop
// overhead per unit work. Stage = 2 k-subtiles (A 2x28KB, B 2x8KB), NCHUNK=64,
// STAGES=3 (217KB smem). Producer/consumer warp specialization, elected warp-level
// mbarrier arrives, MCTA=224 (7+7 warps), grid=147 (all SMs), cp.async B.

#define NB 32768
#define NI 512
#define NO 64
#define NG 8
#define KTOT 8192
#define MCTA 224
#define KC 128             // K per chunk = 8 i-values * 16 features
#define NCHUNK 64
#define NTHREADS 448
#define NGRID ((NB + MCTA - 1) / MCTA)     // 147
#define STAGES 3

#define ASUB (MCTA * 128)          // 28672: one A k-subtile (224 rows x 128B)
#define BSUB (64 * 128)            // 8192:  one B k-subtile
#define ABYTES (2 * ASUB)          // 57344
#define BBYTES (2 * BSUB)          // 16384
#define BUFSZ  (ABYTES + BBYTES)   // 73728
#define SMEM_BUF0 1024
#define SMEM_TOTAL (SMEM_BUF0 + STAGES * BUFSZ)   // 222208 (< 228KB cap)

// repacked coeffs: Wt[o][k], k = i*16 + f; f<8: cos freq f+1, f>=8: sin freq f-7
__device__ __half g_Wt[NO * KTOT];

// ---------------- helpers ----------------
__device__ __forceinline__ uint32_t smem_u32(const void* p) {
    uint32_t a;
    asm("{ .reg .u64 t; cvta.to.shared.u64 t, %1; cvt.u32.u64 %0, t; }" : "=r"(a) : "l"(p));
    return a;
}

#define SW128(o) ((o) ^ (((o) >> 3) & 0x70))

#define LDSM_X4(r0, r1, r2, r3, addr) \
    asm volatile("ldmatrix.sync.aligned.m8n8.x4.shared.b16 {%0,%1,%2,%3}, [%4];" \
                 : "=r"(r0), "=r"(r1), "=r"(r2), "=r"(r3) : "r"(addr))

#define CP_ASYNC16(dst, src) \
    asm volatile("cp.async.ca.shared.global [%0], [%1], 16;" \
                 :: "r"(dst), "l"(src) : "memory")
#define CP_COMMIT() asm volatile("cp.async.commit_group;" ::: "memory")
#define CP_WAIT0()  asm volatile("cp.async.wait_group 0;" ::: "memory")

#define MBAR_INIT(a, c) \
    asm volatile("mbarrier.init.shared.b64 [%0], %1;" :: "r"((uint32_t)(a)), "r"((uint32_t)(c)) : "memory")
#define MBAR_ARRIVE(a) \
    asm volatile("mbarrier.arrive.release.cta.shared::cta.b64 _, [%0];" :: "r"((uint32_t)(a)) : "memory")

#define MBAR_WAIT_PARITY(addr, parity) do {                                        \
    uint32_t _mbar = (uint32_t)(addr);                                             \
    uint32_t _par = (uint32_t)(parity);                                            \
    uint32_t _done;                                                                \
    asm volatile("{\n\t.reg .pred p;\n\t"                                          \
        "mbarrier.try_wait.parity.acquire.cta.shared::cta.b64 p, [%1], %2;\n\t"    \
        "selp.b32 %0, 1, 0, p;\n\t}"                                               \
        : "=r"(_done) : "r"(_mbar), "r"(_par) : "memory");                         \
    if (!_done) {                                                                  \
        asm volatile("{\n\t.reg .pred P1;\n\t"                                     \
            "WAIT_LOOP_%=:\n\t"                                                    \
            "mbarrier.try_wait.parity.acquire.cta.shared::cta.b64 P1, [%0], %1, 0x989680;\n\t" \
            "@P1 bra.uni WAIT_DONE_%=;\n\t"                                        \
            "bra.uni WAIT_LOOP_%=;\n\t"                                            \
            "WAIT_DONE_%=:\n\t}"                                                   \
            :: "r"(_mbar), "r"(_par) : "memory");                                  \
    }                                                                              \
} while (0)

__device__ __forceinline__ void mma16816(float* d, const uint32_t* a,
                                         uint32_t b0, uint32_t b1) {
    asm volatile(
        "mma.sync.aligned.m16n8k16.row.col.f32.f16.f16.f32 "
        "{%0,%1,%2,%3}, {%4,%5,%6,%7}, {%8,%9}, {%0,%1,%2,%3};"
        : "+f"(d[0]), "+f"(d[1]), "+f"(d[2]), "+f"(d[3])
        : "r"(a[0]), "r"(a[1]), "r"(a[2]), "r"(a[3]), "r"(b0), "r"(b1));
}

// ---------------- prep: repack coeffs (2,I,O,G) f32 -> Wt[o][k] fp16 ----------------
__global__ void fkan_prep(const float* __restrict__ cf) {
    int idx = blockIdx.x * blockDim.x + threadIdx.x;
    if (idx >= NO * KTOT) return;
    int o = idx >> 13;
    int k = idx & (KTOT - 1);
    int i = k >> 4;
    int f = k & 15;
    int t = f >> 3;               // 0 = cos, 1 = sin
    int g = f & 7;                // freq-1
    float v = cf[(((t * NI) + i) * NO + o) * NG + g];
    g_Wt[o * KTOT + k] = __float2half(v);
}

// ---------------- main fused kernel ----------------
__global__ void __launch_bounds__(NTHREADS, 1)
fkan_main(const float* __restrict__ x, const float* __restrict__ bias,
          float* __restrict__ out) {
    extern __shared__ __align__(1024) char smem[];
    const uint32_t sbase = smem_u32(smem);

    const int tid = threadIdx.x;
    const int w = tid >> 5;
    const int lane = tid & 31;
    const int ctaRow = blockIdx.x * MCTA;

    // barriers: full[s] at s*16, empty[s] at s*16+8 — WARP-level counts (7 each)
    if (tid == 0) {
        #pragma unroll
        for (int s = 0; s < STAGES; ++s) {
            MBAR_INIT(sbase + s * 16, 7);         // full: 7 producer warps
            MBAR_INIT(sbase + s * 16 + 8, 7);     // empty: 7 consumer warps
        }
    }
    __syncthreads();

    if (w < 7) {
        // ================= CONSUMER: MMA warps =================
        const int mw = w;                   // rows mw*32 .. +31
        const uint32_t a_ls0 = SW128((uint32_t)((mw * 32 + (lane & 15)) * 128 +
                                                ((lane >> 4) << 4)));
        const uint32_t a_ls1 = SW128((uint32_t)((mw * 32 + 16 + (lane & 15)) * 128 +
                                                ((lane >> 4) << 4)));
        const uint32_t bl = (uint32_t)((lane & 7) + ((lane >> 4) << 3));
        const uint32_t bbo = (uint32_t)(((lane >> 3) & 1) << 4);
        uint32_t b_ls[4];
        #pragma unroll
        for (int t = 0; t < 4; ++t)
            b_ls[t] = SW128((uint32_t)((t * 16 + bl) * 128 + bbo));

        float acc[2][8][4];
        #pragma unroll
        for (int mi = 0; mi < 2; ++mi)
            #pragma unroll
            for (int j = 0; j < 8; ++j)
                #pragma unroll
                for (int q = 0; q < 4; ++q) acc[mi][j][q] = 0.0f;

        int s = 0, mpar = 0;
        #pragma unroll 1
        for (int c = 0; c < NCHUNK; ++c) {
            MBAR_WAIT_PARITY(sbase + s * 16, mpar);            // wait full[s]
            const uint32_t buf = sbase + SMEM_BUF0 + (uint32_t)s * BUFSZ;

            #pragma unroll
            for (int kb = 0; kb < 2; ++kb) {
                const uint32_t aB = buf + (uint32_t)kb * ASUB;
                const uint32_t bB = buf + ABYTES + (uint32_t)kb * BSUB;
                #pragma unroll
                for (int ks = 0; ks < 4; ++ks) {
                    const uint32_t kx = (uint32_t)(ks << 5);
                    uint32_t a0[4], a1[4], b[16];
                    LDSM_X4(a0[0], a0[1], a0[2], a0[3], aB + (a_ls0 ^ kx));
                    LDSM_X4(a1[0], a1[1], a1[2], a1[3], aB + (a_ls1 ^ kx));
                    #pragma unroll
                    for (int t = 0; t < 4; ++t)
                        LDSM_X4(b[4 * t], b[4 * t + 1], b[4 * t + 2], b[4 * t + 3],
                                bB + (b_ls[t] ^ kx));
                    #pragma unroll
                    for (int j = 0; j < 8; ++j) {
                        const int t = j >> 1;
                        const int hi = (j & 1) << 1;
                        mma16816(acc[0][j], a0, b[4 * t + hi], b[4 * t + hi + 1]);
                        mma16816(acc[1][j], a1, b[4 * t + hi], b[4 * t + hi + 1]);
                    }
                }
            }

            __syncwarp();
            if (lane == 0)
                MBAR_ARRIVE(sbase + s * 16 + 8);               // elected arrive empty[s]
            if (++s == STAGES) { s = 0; mpar ^= 1; }
        }

        // ---- epilogue: acc (+bias) -> out, predicated for the tail CTA ----
        const int gr = lane >> 2;
        const int gc = (lane & 3) << 1;
        #pragma unroll
        for (int mi = 0; mi < 2; ++mi) {
            const int row0 = ctaRow + mw * 32 + mi * 16 + gr;
            #pragma unroll
            for (int j = 0; j < 8; ++j) {
                const int col = j * 8 + gc;
                float2 bb2 = *(const float2*)(bias + col);
                float2 v0, v1;
                v0.x = acc[mi][j][0] + bb2.x; v0.y = acc[mi][j][1] + bb2.y;
                v1.x = acc[mi][j][2] + bb2.x; v1.y = acc[mi][j][3] + bb2.y;
                if (row0 < NB)
                    *(float2*)(out + (size_t)row0 * NO + col) = v0;
                if (row0 + 8 < NB)
                    *(float2*)(out + (size_t)(row0 + 8) * NO + col) = v1;
            }
        }
    } else {
        // ================= PRODUCER: feature warps =================
        const int p = tid - 224;            // 0..223
        const int row = p;                  // one full row (8 i-units) per thread
        const int grow = ctaRow + row;
        const int crow = (grow < NB) ? grow : (NB - 1);    // clamp for tail CTA
        const float* xrow = x + (size_t)crow * NI;
        uint32_t fst[8];                    // per i&3: two 16B halves
        #pragma unroll
        for (int j = 0; j < 4; ++j) {
            fst[2 * j]     = SW128((uint32_t)(row * 128 + j * 32));
            fst[2 * j + 1] = SW128((uint32_t)(row * 128 + j * 32 + 16));
        }
        // B loader: threads p<128; bo = p>>1 (0..63), half = p&1 -> k-subtile,
        // 8 x 16B units (one 128B swizzle row) per thread
        const bool doB = (p < 128);
        const int bo = p >> 1;
        const int bhalf = p & 1;
        const __half* wsrc = g_Wt + bo * KTOT + bhalf * 64;   // 64 halves = 128B
        uint32_t b_st[8];
        #pragma unroll
        for (int u = 0; u < 8; ++u)
            b_st[u] = (uint32_t)(ABYTES + bhalf * BSUB) +
                      SW128((uint32_t)(bo * 128 + u * 16));

        float4 xa = *(const float4*)(xrow);          // chunk 0: i 0..3
        float4 xb = *(const float4*)(xrow + 4);      //          i 4..7

        int s = 0, mpar = 0;
        #pragma unroll 1
        for (int c = 0; c < NCHUNK; ++c) {
            // prefetch next chunk's x (clamped)
            const int cp = (c + 1 < NCHUNK) ? c + 1 : NCHUNK - 1;
            float4 xan = *(const float4*)(xrow + cp * 8);
            float4 xbn = *(const float4*)(xrow + cp * 8 + 4);

            MBAR_WAIT_PARITY(sbase + s * 16 + 8, mpar ^ 1);    // wait empty[s]
            const uint32_t buf = sbase + SMEM_BUF0 + (uint32_t)s * BUFSZ;

            // B tile via cp.async: 8 x 16B per loader thread
            if (doB) {
                #pragma unroll
                for (int u = 0; u < 8; ++u)
                    CP_ASYNC16(buf + b_st[u], wsrc + (size_t)c * KC + u * 8);
            }
            CP_COMMIT();

            // A features: 8 i-units for this row (two k-subtiles)
            const float xs[8] = {xa.x, xa.y, xa.z, xa.w, xb.x, xb.y, xb.z, xb.w};
            #pragma unroll
            for (int j = 0; j < 8; ++j) {
                float s1, c1;
                __sincosf(xs[j], &s1, &c1);
                float t2 = c1 + c1;
                float ck[8], sk[8];
                ck[0] = c1; sk[0] = s1;
                float cm2 = 1.0f, sm2 = 0.0f;
                #pragma unroll
                for (int k = 1; k < 8; ++k) {
                    float cn = fmaf(t2, ck[k - 1], -cm2);
                    float sn = fmaf(t2, sk[k - 1], -sm2);
                    cm2 = ck[k - 1]; sm2 = sk[k - 1];
                    ck[k] = cn; sk[k] = sn;
                }
                __half2 h[8];
                h[0] = __floats2half2_rn(ck[0], ck[1]);
                h[1] = __floats2half2_rn(ck[2], ck[3]);
                h[2] = __floats2half2_rn(ck[4], ck[5]);
                h[3] = __floats2half2_rn(ck[6], ck[7]);
                h[4] = __floats2half2_rn(sk[0], sk[1]);
                h[5] = __floats2half2_rn(sk[2], sk[3]);
                h[6] = __floats2half2_rn(sk[4], sk[5]);
                h[7] = __floats2half2_rn(sk[6], sk[7]);
                uint4 vc, vs;
                vc.x = *(uint32_t*)&h[0]; vc.y = *(uint32_t*)&h[1];
                vc.z = *(uint32_t*)&h[2]; vc.w = *(uint32_t*)&h[3];
                vs.x = *(uint32_t*)&h[4]; vs.y = *(uint32_t*)&h[5];
                vs.z = *(uint32_t*)&h[6]; vs.w = *(uint32_t*)&h[7];
                const uint32_t so = (buf - sbase) + (uint32_t)((j >> 2) * ASUB);
                *(uint4*)(smem + so + fst[2 * (j & 3)]) = vc;
                *(uint4*)(smem + so + fst[2 * (j & 3) + 1]) = vs;
            }

            CP_WAIT0();                        // B copies done (this thread)
            __syncwarp();                      // order warp's STS + copies to lane 0
            if (lane == 0)
                MBAR_ARRIVE(sbase + s * 16);   // elected arrive full[s]

            xa = xan; xb = xbn;
            if (++s == STAGES) { s = 0; mpar ^= 1; }
        }
    }
}

// ---------------- launch ----------------
extern "C" void kernel_launch(void* const* d_in, const int* in_sizes, int n_in,
                              void* d_out, int out_size) {
    const float* x    = (const float*)d_in[0];
    const float* cf   = (const float*)d_in[1];
    const float* bias = (const float*)d_in[2];
    float* out        = (float*)d_out;

    static bool attr_set = false;
    if (!attr_set) {
        cudaFuncSetAttribute(fkan_main, cudaFuncAttributeMaxDynamicSharedMemorySize,
                             SMEM_TOTAL);
        attr_set = true;
    }

    fkan_prep<<<(NO * KTOT + 255) / 256, 256>>>(cf);
    fkan_main<<<NGRID, NTHREADS, SMEM_TOTAL>>>(x, bias, out);
}

// round 17
// speedup vs baseline: 1.2610x; 1.2610x over previous
#include <cuda_runtime.h>
#include <cuda_fp16.h>
#include <cstdint>

// Fourier-KAN: out[b,o] = bias[o] + sum_{i,k} cos(k x[b,i]) c0[i,o,k-1] + sin(k x) c1[i,o,k-1]
// B=32768, I=512, O=64, G=8  ->  GEMM M=32768, N=64, K=8192, fp16 features on the fly.
// R17 = R15 (best: 118.8us) with STAGES 4 -> 6 (more producer run-ahead; 222KB smem).
// Producer/consumer warp specialization, elected warp-level mbarrier arrives,
// MCTA=224 (7+7 warps), grid=147 (all SMs), KC=64, cp.async B.

#define NB 32768
#define NI 512
#define NO 64
#define NG 8
#define KTOT 8192
#define MCTA 224
#define KC 64              // K per chunk = 4 i-values * 16 features
#define NCHUNK 128
#define NTHREADS 448
#define NGRID ((NB + MCTA - 1) / MCTA)     // 147
#define STAGES 6

#define ABYTES (MCTA * 128)        // 28672
#define BBYTES (64 * 128)          // 8192
#define BUFSZ  (ABYTES + BBYTES)   // 36864
#define SMEM_BUF0 1024
#define SMEM_TOTAL (SMEM_BUF0 + STAGES * BUFSZ)   // 222208

// repacked coeffs: Wt[o][k], k = i*16 + f; f<8: cos freq f+1, f>=8: sin freq f-7
__device__ __half g_Wt[NO * KTOT];

// ---------------- helpers ----------------
__device__ __forceinline__ uint32_t smem_u32(const void* p) {
    uint32_t a;
    asm("{ .reg .u64 t; cvta.to.shared.u64 t, %1; cvt.u32.u64 %0, t; }" : "=r"(a) : "l"(p));
    return a;
}

#define SW128(o) ((o) ^ (((o) >> 3) & 0x70))

#define LDSM_X4(r0, r1, r2, r3, addr) \
    asm volatile("ldmatrix.sync.aligned.m8n8.x4.shared.b16 {%0,%1,%2,%3}, [%4];" \
                 : "=r"(r0), "=r"(r1), "=r"(r2), "=r"(r3) : "r"(addr))

#define CP_ASYNC16(dst, src) \
    asm volatile("cp.async.ca.shared.global [%0], [%1], 16;" \
                 :: "r"(dst), "l"(src) : "memory")
#define CP_COMMIT() asm volatile("cp.async.commit_group;" ::: "memory")
#define CP_WAIT0()  asm volatile("cp.async.wait_group 0;" ::: "memory")

#define MBAR_INIT(a, c) \
    asm volatile("mbarrier.init.shared.b64 [%0], %1;" :: "r"((uint32_t)(a)), "r"((uint32_t)(c)) : "memory")
#define MBAR_ARRIVE(a) \
    asm volatile("mbarrier.arrive.release.cta.shared::cta.b64 _, [%0];" :: "r"((uint32_t)(a)) : "memory")

#define MBAR_WAIT_PARITY(addr, parity) do {                                        \
    uint32_t _mbar = (uint32_t)(addr);                                             \
    uint32_t _par = (uint32_t)(parity);                                            \
    uint32_t _done;                                                                \
    asm volatile("{\n\t.reg .pred p;\n\t"                                          \
        "mbarrier.try_wait.parity.acquire.cta.shared::cta.b64 p, [%1], %2;\n\t"    \
        "selp.b32 %0, 1, 0, p;\n\t}"                                               \
        : "=r"(_done) : "r"(_mbar), "r"(_par) : "memory");                         \
    if (!_done) {                                                                  \
        asm volatile("{\n\t.reg .pred P1;\n\t"                                     \
            "WAIT_LOOP_%=:\n\t"                                                    \
            "mbarrier.try_wait.parity.acquire.cta.shared::cta.b64 P1, [%0], %1, 0x989680;\n\t" \
            "@P1 bra.uni WAIT_DONE_%=;\n\t"                                        \
            "bra.uni WAIT_LOOP_%=;\n\t"                                            \
            "WAIT_DONE_%=:\n\t}"                                                   \
            :: "r"(_mbar), "r"(_par) : "memory");                                  \
    }                                                                              \
} while (0)

__device__ __forceinline__ void mma16816(float* d, const uint32_t* a,
                                         uint32_t b0, uint32_t b1) {
    asm volatile(
        "mma.sync.aligned.m16n8k16.row.col.f32.f16.f16.f32 "
        "{%0,%1,%2,%3}, {%4,%5,%6,%7}, {%8,%9}, {%0,%1,%2,%3};"
        : "+f"(d[0]), "+f"(d[1]), "+f"(d[2]), "+f"(d[3])
        : "r"(a[0]), "r"(a[1]), "r"(a[2]), "r"(a[3]), "r"(b0), "r"(b1));
}

// ---------------- prep: repack coeffs (2,I,O,G) f32 -> Wt[o][k] fp16 ----------------
__global__ void fkan_prep(const float* __restrict__ cf) {
    int idx = blockIdx.x * blockDim.x + threadIdx.x;
    if (idx >= NO * KTOT) return;
    int o = idx >> 13;
    int k = idx & (KTOT - 1);
    int i = k >> 4;
    int f = k & 15;
    int t = f >> 3;               // 0 = cos, 1 = sin
    int g = f & 7;                // freq-1
    float v = cf[(((t * NI) + i) * NO + o) * NG + g];
    g_Wt[o * KTOT + k] = __float2half(v);
}

// ---------------- main fused kernel ----------------
__global__ void __launch_bounds__(NTHREADS, 1)
fkan_main(const float* __restrict__ x, const float* __restrict__ bias,
          float* __restrict__ out) {
    extern __shared__ __align__(1024) char smem[];
    const uint32_t sbase = smem_u32(smem);

    const int tid = threadIdx.x;
    const int w = tid >> 5;
    const int lane = tid & 31;
    const int ctaRow = blockIdx.x * MCTA;

    // barriers: full[s] at s*16, empty[s] at s*16+8 — WARP-level counts (7 each)
    if (tid == 0) {
        #pragma unroll
        for (int s = 0; s < STAGES; ++s) {
            MBAR_INIT(sbase + s * 16, 7);         // full: 7 producer warps
            MBAR_INIT(sbase + s * 16 + 8, 7);     // empty: 7 consumer warps
        }
    }
    __syncthreads();

    if (w < 7) {
        // ================= CONSUMER: MMA warps =================
        const int mw = w;                   // rows mw*32 .. +31
        const uint32_t a_ls0 = SW128((uint32_t)((mw * 32 + (lane & 15)) * 128 +
                                                ((lane >> 4) << 4)));
        const uint32_t a_ls1 = SW128((uint32_t)((mw * 32 + 16 + (lane & 15)) * 128 +
                                                ((lane >> 4) << 4)));
        const uint32_t bl = (uint32_t)((lane & 7) + ((lane >> 4) << 3));
        const uint32_t bbo = (uint32_t)(((lane >> 3) & 1) << 4);
        uint32_t b_ls[4];
        #pragma unroll
        for (int t = 0; t < 4; ++t)
            b_ls[t] = SW128((uint32_t)((t * 16 + bl) * 128 + bbo));

        float acc[2][8][4];
        #pragma unroll
        for (int mi = 0; mi < 2; ++mi)
            #pragma unroll
            for (int j = 0; j < 8; ++j)
                #pragma unroll
                for (int q = 0; q < 4; ++q) acc[mi][j][q] = 0.0f;

        int s = 0, mpar = 0;
        #pragma unroll 1
        for (int c = 0; c < NCHUNK; ++c) {
            MBAR_WAIT_PARITY(sbase + s * 16, mpar);            // wait full[s]
            const uint32_t aB = sbase + SMEM_BUF0 + (uint32_t)s * BUFSZ;
            const uint32_t bB = aB + ABYTES;

            #pragma unroll
            for (int ks = 0; ks < 4; ++ks) {
                const uint32_t kx = (uint32_t)(ks << 5);
                uint32_t a0[4], a1[4], b[16];
                LDSM_X4(a0[0], a0[1], a0[2], a0[3], aB + (a_ls0 ^ kx));
                LDSM_X4(a1[0], a1[1], a1[2], a1[3], aB + (a_ls1 ^ kx));
                #pragma unroll
                for (int t = 0; t < 4; ++t)
                    LDSM_X4(b[4 * t], b[4 * t + 1], b[4 * t + 2], b[4 * t + 3],
                            bB + (b_ls[t] ^ kx));
                #pragma unroll
                for (int j = 0; j < 8; ++j) {
                    const int t = j >> 1;
                    const int hi = (j & 1) << 1;
                    mma16816(acc[0][j], a0, b[4 * t + hi], b[4 * t + hi + 1]);
                    mma16816(acc[1][j], a1, b[4 * t + hi], b[4 * t + hi + 1]);
                }
            }

            __syncwarp();
            if (lane == 0)
                MBAR_ARRIVE(sbase + s * 16 + 8);               // elected arrive empty[s]
            if (++s == STAGES) { s = 0; mpar ^= 1; }
        }

        // ---- epilogue: acc (+bias) -> out, predicated for the tail CTA ----
        const int gr = lane >> 2;
        const int gc = (lane & 3) << 1;
        #pragma unroll
        for (int mi = 0; mi < 2; ++mi) {
            const int row0 = ctaRow + mw * 32 + mi * 16 + gr;
            #pragma unroll
            for (int j = 0; j < 8; ++j) {
                const int col = j * 8 + gc;
                float2 bb2 = *(const float2*)(bias + col);
                float2 v0, v1;
                v0.x = acc[mi][j][0] + bb2.x; v0.y = acc[mi][j][1] + bb2.y;
                v1.x = acc[mi][j][2] + bb2.x; v1.y = acc[mi][j][3] + bb2.y;
                if (row0 < NB)
                    *(float2*)(out + (size_t)row0 * NO + col) = v0;
                if (row0 + 8 < NB)
                    *(float2*)(out + (size_t)(row0 + 8) * NO + col) = v1;
            }
        }
    } else {
        // ================= PRODUCER: feature warps =================
        const int p = tid - 224;            // 0..223
        const int row = p;                  // one full row (4 i-units) per thread
        const int grow = ctaRow + row;
        const int crow = (grow < NB) ? grow : (NB - 1);    // clamp for tail CTA
        const float* xrow = x + (size_t)crow * NI;
        uint32_t fst[8];
        #pragma unroll
        for (int j = 0; j < 4; ++j) {
            fst[2 * j]     = SW128((uint32_t)(row * 128 + j * 32));
            fst[2 * j + 1] = SW128((uint32_t)(row * 128 + j * 32 + 16));
        }
        // B loader: threads p<128 handle it; bo = p>>1 (0..63), 4 x 16B units
        const bool doB = (p < 128);
        const int bo = p >> 1;
        const int buh = (p & 1) << 2;
        const __half* wsrc = g_Wt + bo * KTOT + buh * 8;
        uint32_t b_st[4];
        #pragma unroll
        for (int u = 0; u < 4; ++u)
            b_st[u] = SW128((uint32_t)(bo * 128 + (buh + u) * 16));

        float4 xv = *(const float4*)(xrow);      // chunk 0

        int s = 0, mpar = 0;
        #pragma unroll 1
        for (int c = 0; c < NCHUNK; ++c) {
            // prefetch next chunk's x (clamped)
            const int cp = (c + 1 < NCHUNK) ? c + 1 : NCHUNK - 1;
            float4 xn = *(const float4*)(xrow + cp * 4);

            MBAR_WAIT_PARITY(sbase + s * 16 + 8, mpar ^ 1);    // wait empty[s]
            const uint32_t aB = sbase + SMEM_BUF0 + (uint32_t)s * BUFSZ;
            const uint32_t bB = aB + ABYTES;

            // B tile via cp.async
            if (doB) {
                #pragma unroll
                for (int u = 0; u < 4; ++u)
                    CP_ASYNC16(bB + b_st[u], wsrc + (size_t)c * KC + u * 8);
            }
            CP_COMMIT();

            // A features: 4 i-units for this row
            const float xs[4] = {xv.x, xv.y, xv.z, xv.w};
            #pragma unroll
            for (int j = 0; j < 4; ++j) {
                float s1, c1;
                __sincosf(xs[j], &s1, &c1);
                float t2 = c1 + c1;
                float ck[8], sk[8];
                ck[0] = c1; sk[0] = s1;
                float cm2 = 1.0f, sm2 = 0.0f;
                #pragma unroll
                for (int k = 1; k < 8; ++k) {
                    float cn = fmaf(t2, ck[k - 1], -cm2);
                    float sn = fmaf(t2, sk[k - 1], -sm2);
                    cm2 = ck[k - 1]; sm2 = sk[k - 1];
                    ck[k] = cn; sk[k] = sn;
                }
                __half2 h[8];
                h[0] = __floats2half2_rn(ck[0], ck[1]);
                h[1] = __floats2half2_rn(ck[2], ck[3]);
                h[2] = __floats2half2_rn(ck[4], ck[5]);
                h[3] = __floats2half2_rn(ck[6], ck[7]);
                h[4] = __floats2half2_rn(sk[0], sk[1]);
                h[5] = __floats2half2_rn(sk[2], sk[3]);
                h[6] = __floats2half2_rn(sk[4], sk[5]);
                h[7] = __floats2half2_rn(sk[6], sk[7]);
                uint4 vc, vs;
                vc.x = *(uint32_t*)&h[0]; vc.y = *(uint32_t*)&h[1];
                vc.z = *(uint32_t*)&h[2]; vc.w = *(uint32_t*)&h[3];
                vs.x = *(uint32_t*)&h[4]; vs.y = *(uint32_t*)&h[5];
                vs.z = *(uint32_t*)&h[6]; vs.w = *(uint32_t*)&h[7];
                *(uint4*)(smem + (aB - sbase) + fst[2 * j]) = vc;
                *(uint4*)(smem + (aB - sbase) + fst[2 * j + 1]) = vs;
            }

            CP_WAIT0();                        // B copies done (this thread)
            __syncwarp();                      // order warp's STS + copies to lane 0
            if (lane == 0)
                MBAR_ARRIVE(sbase + s * 16);   // elected arrive full[s]

            xv = xn;
            if (++s == STAGES) { s = 0; mpar ^= 1; }
        }
    }
}

// ---------------- launch ----------------
extern "C" void kernel_launch(void* const* d_in, const int* in_sizes, int n_in,
                              void* d_out, int out_size) {
    const float* x    = (const float*)d_in[0];
    const float* cf   = (const float*)d_in[1];
    const float* bias = (const float*)d_in[2];
    float* out        = (float*)d_out;

    static bool attr_set = false;
    if (!attr_set) {
        cudaFuncSetAttribute(fkan_main, cudaFuncAttributeMaxDynamicSharedMemorySize,
                             SMEM_TOTAL);
        attr_set = true;
    }

    fkan_prep<<<(NO * KTOT + 255) / 256, 256>>>(cf);
    fkan_main<<<NGRID, NTHREADS, SMEM_TOTAL>>>(x, bias, out);
}